// round 13
// baseline (speedup 1.0000x reference)
#include <cuda_runtime.h>
#include <cuda_fp16.h>
#include <cstdint>

// Gene Linear Attention — fp16 mma.sync pipeline v11.
// 128-thread CTAs: 4 warps, 2x2 grid of 64x64 warp tiles (max MMA density),
// 2 CTAs/SM (cross-CTA latency hiding). CTA tile 128x128, S=5 pair-chunk pipeline.

#define RR   64
#define CC   2048
#define EE   128
#define HH   8
#define HDIM 16
#define DD   1024   // RR*HDIM

typedef __half hf;

// ---------------- device global scratch ----------------
__device__ float g_ksum[HH * DD];
__device__ float g_ball[3 * EE];
__device__ int   g_ctx_done;

__device__ hf g_xh[RR * CC * EE];
__device__ hf g_Wallh[3 * EE * EE];     // Wq|Wk|Wv stacked rows

__device__ hf g_Qh[HH * CC * DD];       // softmaxed+scaled q [h][c][d]
__device__ hf g_Kexp[HH * CC * DD];     // exp(k logits) fp16 [h][n][d]
__device__ hf g_Vh[HH * CC * DD];       // v fp16 [h][n][e]
__device__ hf g_Kh[HH * CC * DD];       // softmaxed k [h][n][d]
__device__ hf g_CTh[HH * DD * DD];      // ctxT [h][col=e][d]

// ---------------- PTX helpers ----------------
__device__ __forceinline__ uint32_t cvta(const void* p) {
    return (uint32_t)__cvta_generic_to_shared(p);
}
__device__ __forceinline__ void cp16(uint32_t dst, const void* src) {
    asm volatile("cp.async.cg.shared.global [%0], [%1], 16;\n" :: "r"(dst), "l"(src));
}
#define CP_COMMIT() asm volatile("cp.async.commit_group;\n" ::)

__device__ __forceinline__ void ldm4(uint32_t (&a)[4], uint32_t addr) {
    asm volatile("ldmatrix.sync.aligned.m8n8.x4.shared.b16 {%0,%1,%2,%3}, [%4];"
                 : "=r"(a[0]), "=r"(a[1]), "=r"(a[2]), "=r"(a[3]) : "r"(addr));
}
__device__ __forceinline__ void ldm4t(uint32_t (&a)[4], uint32_t addr) {
    asm volatile("ldmatrix.sync.aligned.m8n8.x4.trans.shared.b16 {%0,%1,%2,%3}, [%4];"
                 : "=r"(a[0]), "=r"(a[1]), "=r"(a[2]), "=r"(a[3]) : "r"(addr));
}
__device__ __forceinline__ void mma16816(float (&c)[4], const uint32_t (&a)[4],
                                         const uint32_t b0, const uint32_t b1) {
    asm volatile(
        "mma.sync.aligned.m16n8k16.row.col.f32.f16.f16.f32 "
        "{%0,%1,%2,%3}, {%4,%5,%6,%7}, {%8,%9}, {%0,%1,%2,%3};"
        : "+f"(c[0]), "+f"(c[1]), "+f"(c[2]), "+f"(c[3])
        : "r"(a[0]), "r"(a[1]), "r"(a[2]), "r"(a[3]), "r"(b0), "r"(b1));
}

// ---------------------------------------------------------------------------
// Tile config: CTA 128x128, 128 threads, warps 2x2 (64x64 each), BK=32, S=5
// ---------------------------------------------------------------------------
#define BM 128
#define BN 128
#define BK 32
#define NTHR 128
#define LDSS 40                       // NT half stride (32 + 8 pad)
#define OFF_BH (BM * LDSS)
#define GSTAGE ((BM + BN) * LDSS)     // 10240 halfs per stage
#define NSTAGE 5
#define SMEM_BYTES (NSTAGE * GSTAGE * 2)   // 102400

// TN layout inside a stage: A 32x128 (stride 136), B 32x128 (stride 136)
#define TLDA 136
#define TLDB 136
#define OFF_TB (32 * TLDA)

// ---------------- NT mainloop (A[m][k], B[n][k]) ----------------
__device__ __forceinline__ void gemm_nt(
    const hf* __restrict__ pA, const hf* __restrict__ pB,
    int ldA, int ldB, int Kdim, int m0, int n0,
    hf* smem, int tid, int lane, int wm, int wn,
    float (&acc)[4][8][4])
{
    auto load_stage = [&](int st, int k0) {
        hf* s = smem + st * GSTAGE;
#pragma unroll
        for (int t = 0; t < 4; t++) {
            int slot = tid + t * NTHR;    // 512 slots: 128 rows x 4 segs
            int r = slot >> 2, seg = slot & 3;
            cp16(cvta(s + r * LDSS + seg * 8), pA + (size_t)(m0 + r) * ldA + k0 + seg * 8);
        }
#pragma unroll
        for (int t = 0; t < 4; t++) {
            int slot = tid + t * NTHR;
            int r = slot >> 2, seg = slot & 3;
            cp16(cvta(s + OFF_BH + r * LDSS + seg * 8), pB + (size_t)(n0 + r) * ldB + k0 + seg * 8);
        }
    };
    auto compute_stage = [&](int st) {
        const hf* s = smem + st * GSTAGE;
        const uint32_t baseA = cvta(s);
        const uint32_t baseB = cvta(s + OFF_BH);
#pragma unroll
        for (int kk = 0; kk < 2; kk++) {
            uint32_t a[4][4], b[4][4];
#pragma unroll
            for (int mi = 0; mi < 4; mi++) {
                int m = wm * 64 + mi * 16 + (lane & 15);
                ldm4(a[mi], baseA + (uint32_t)(m * LDSS + kk * 16 + (lane >> 4) * 8) * 2);
            }
#pragma unroll
            for (int nb = 0; nb < 4; nb++) {
                int n = wn * 64 + nb * 16 + ((lane >> 4) << 3) + (lane & 7);
                ldm4(b[nb], baseB + (uint32_t)(n * LDSS + kk * 16 + ((lane >> 3) & 1) * 8) * 2);
            }
#pragma unroll
            for (int mi = 0; mi < 4; mi++)
#pragma unroll
                for (int nb = 0; nb < 4; nb++) {
                    mma16816(acc[mi][nb * 2], a[mi], b[nb][0], b[nb][1]);
                    mma16816(acc[mi][nb * 2 + 1], a[mi], b[nb][2], b[nb][3]);
                }
        }
    };

    const int nk = Kdim / BK;
#pragma unroll 1
    for (int s = 0; s < 3; s++) { if (s < nk) load_stage(s, s * BK); CP_COMMIT(); }
#pragma unroll 1
    for (int p = 0; p < nk; p += 2) {
        asm volatile("cp.async.wait_group 1;\n" ::);
        __syncthreads();
        compute_stage(p % NSTAGE);
        if (p + 3 < nk) load_stage((p + 3) % NSTAGE, (p + 3) * BK);
        CP_COMMIT();
        compute_stage((p + 1) % NSTAGE);
        if (p + 4 < nk) load_stage((p + 4) % NSTAGE, (p + 4) * BK);
        CP_COMMIT();
    }
}

// ---------------- TN mainloop (A[k][m], B[k][n]; ldmatrix.trans) ----------------
__device__ __forceinline__ void gemm_tn(
    const hf* __restrict__ pA, const hf* __restrict__ pB,
    int ldA, int ldB, int Kdim, int m0, int n0,
    hf* smem, int tid, int lane, int wm, int wn,
    float (&acc)[4][8][4])
{
    auto load_stage = [&](int st, int k0) {
        hf* s = smem + st * GSTAGE;
#pragma unroll
        for (int t = 0; t < 4; t++) {
            int slot = tid + t * NTHR;    // 512 slots: 32 rows x 16 segs
            int r = slot >> 4, seg = slot & 15;
            cp16(cvta(s + r * TLDA + seg * 8), pA + (size_t)(k0 + r) * ldA + m0 + seg * 8);
        }
#pragma unroll
        for (int t = 0; t < 4; t++) {
            int slot = tid + t * NTHR;
            int r = slot >> 4, seg = slot & 15;
            cp16(cvta(s + OFF_TB + r * TLDB + seg * 8), pB + (size_t)(k0 + r) * ldB + n0 + seg * 8);
        }
    };
    auto compute_stage = [&](int st) {
        const hf* s = smem + st * GSTAGE;
        const uint32_t baseA = cvta(s);
        const uint32_t baseB = cvta(s + OFF_TB);
#pragma unroll
        for (int kk = 0; kk < 2; kk++) {
            uint32_t a[4][4], b[4][4];
            int krA = kk * 16 + (lane & 7) + ((lane >> 4) & 1) * 8;
            int krB = kk * 16 + (lane & 7) + ((lane >> 3) & 1) * 8;
#pragma unroll
            for (int mi = 0; mi < 4; mi++) {
                int m = wm * 64 + mi * 16 + ((lane >> 3) & 1) * 8;
                ldm4t(a[mi], baseA + (uint32_t)(krA * TLDA + m) * 2);
            }
#pragma unroll
            for (int nb = 0; nb < 4; nb++) {
                int n = wn * 64 + nb * 16 + ((lane >> 4) & 1) * 8;
                ldm4t(b[nb], baseB + (uint32_t)(krB * TLDB + n) * 2);
            }
#pragma unroll
            for (int mi = 0; mi < 4; mi++)
#pragma unroll
                for (int nb = 0; nb < 4; nb++) {
                    mma16816(acc[mi][nb * 2], a[mi], b[nb][0], b[nb][1]);
                    mma16816(acc[mi][nb * 2 + 1], a[mi], b[nb][2], b[nb][3]);
                }
        }
    };

    const int nk = Kdim / BK;
#pragma unroll 1
    for (int s = 0; s < 3; s++) { if (s < nk) load_stage(s, s * BK); CP_COMMIT(); }
#pragma unroll 1
    for (int p = 0; p < nk; p += 2) {
        asm volatile("cp.async.wait_group 1;\n" ::);
        __syncthreads();
        compute_stage(p % NSTAGE);
        if (p + 3 < nk) load_stage((p + 3) % NSTAGE, (p + 3) * BK);
        CP_COMMIT();
        compute_stage((p + 1) % NSTAGE);
        if (p + 4 < nk) load_stage((p + 4) % NSTAGE, (p + 4) * BK);
        CP_COMMIT();
    }
}

// ---------------------------------------------------------------------------
// proj kernel: M=131072 (1024 blocks), N=384 (3 blocks), K=128.
// N-block 0: q + fused 16-group softmax; 1: k exp + colsums; 2: v.
// ---------------------------------------------------------------------------
__global__ __launch_bounds__(NTHR, 2) void proj_kernel() {
    extern __shared__ __align__(16) hf smem[];
    const int tid = threadIdx.x, lane = tid & 31, warp = tid >> 5;
    const int wm = warp >> 1, wn = warp & 1;
    const int m0 = blockIdx.y * BM, n0 = blockIdx.x * BN;

    float acc[4][8][4];
#pragma unroll
    for (int i = 0; i < 4; i++)
#pragma unroll
        for (int j = 0; j < 8; j++)
#pragma unroll
            for (int q = 0; q < 4; q++) acc[i][j][q] = 0.f;

    gemm_nt(g_xh, g_Wallh, EE, EE, EE, m0, n0, smem, tid, lane, wm, wn, acc);

    const float* bias = g_ball;
    if (n0 == 0) {
        // ---- q path: fused 16-group softmax (+bias, *1/32) -> g_Qh fp16 ----
#pragma unroll
        for (int mi = 0; mi < 4; mi++) {
            int rc0 = m0 + wm * 64 + mi * 16 + (lane >> 2);
#pragma unroll
            for (int nb = 0; nb < 8; nb += 2) {
                int e0 = wn * 64 + nb * 8 + (lane & 3) * 2;
                float b0 = bias[e0], b1 = bias[e0 + 1];
                float b2 = bias[e0 + 8], b3 = bias[e0 + 9];
                float r0[4] = {acc[mi][nb][0] + b0, acc[mi][nb][1] + b1,
                               acc[mi][nb + 1][0] + b2, acc[mi][nb + 1][1] + b3};
                float r1[4] = {acc[mi][nb][2] + b0, acc[mi][nb][3] + b1,
                               acc[mi][nb + 1][2] + b2, acc[mi][nb + 1][3] + b3};
                float mx0 = fmaxf(fmaxf(r0[0], r0[1]), fmaxf(r0[2], r0[3]));
                float mx1 = fmaxf(fmaxf(r1[0], r1[1]), fmaxf(r1[2], r1[3]));
                mx0 = fmaxf(mx0, __shfl_xor_sync(0xffffffffu, mx0, 1));
                mx0 = fmaxf(mx0, __shfl_xor_sync(0xffffffffu, mx0, 2));
                mx1 = fmaxf(mx1, __shfl_xor_sync(0xffffffffu, mx1, 1));
                mx1 = fmaxf(mx1, __shfl_xor_sync(0xffffffffu, mx1, 2));
                float s0 = 0.f, s1 = 0.f;
#pragma unroll
                for (int q = 0; q < 4; q++) { r0[q] = __expf(r0[q] - mx0); s0 += r0[q]; }
#pragma unroll
                for (int q = 0; q < 4; q++) { r1[q] = __expf(r1[q] - mx1); s1 += r1[q]; }
                s0 += __shfl_xor_sync(0xffffffffu, s0, 1);
                s0 += __shfl_xor_sync(0xffffffffu, s0, 2);
                s1 += __shfl_xor_sync(0xffffffffu, s1, 1);
                s1 += __shfl_xor_sync(0xffffffffu, s1, 2);
                float sc0 = 0.03125f / s0, sc1 = 0.03125f / s1;

                int hh = e0 >> 4, jj = e0 & 15;
#pragma unroll
                for (int rr2 = 0; rr2 < 2; rr2++) {
                    int rc = rc0 + rr2 * 8;
                    int r = rc >> 11, c = rc & (CC - 1);
                    float* vv = rr2 ? r1 : r0;
                    float sc = rr2 ? sc1 : sc0;
                    hf* dst = g_Qh + ((size_t)hh * CC + c) * DD + (r << 4) + jj;
                    *(__half2*)dst = __floats2half2_rn(vv[0] * sc, vv[1] * sc);
                    *(__half2*)(dst + 8) = __floats2half2_rn(vv[2] * sc, vv[3] * sc);
                }
            }
        }
        return;
    }

    if (n0 == 128) {
        // ---- k path: exp(logit+bias) -> g_Kexp + fused column exp-sums ----
        int rB = m0 >> 11;
        float colsum[16];
#pragma unroll
        for (int j = 0; j < 16; j++) colsum[j] = 0.f;

#pragma unroll
        for (int mi = 0; mi < 4; mi++) {
#pragma unroll
            for (int ni = 0; ni < 8; ni++) {
                int grow = m0 + wm * 64 + mi * 16 + (lane >> 2);
                int gcol = n0 + wn * 64 + ni * 8 + (lane & 3) * 2;
                int e = gcol & 127;
                int hh = e >> 4, jj = e & 15;
                float b0 = bias[gcol], b1 = bias[gcol + 1];
#pragma unroll
                for (int rr2 = 0; rr2 < 2; rr2++) {
                    int rc = grow + rr2 * 8;
                    int c = rc & (CC - 1);
                    float e0 = __expf((rr2 ? acc[mi][ni][2] : acc[mi][ni][0]) + b0);
                    float e1 = __expf((rr2 ? acc[mi][ni][3] : acc[mi][ni][1]) + b1);
                    colsum[ni * 2] += e0;
                    colsum[ni * 2 + 1] += e1;
                    *(__half2*)&g_Kexp[((size_t)hh * CC + c) * DD + (rB << 4) + jj] =
                        __floats2half2_rn(e0, e1);
                }
            }
        }
#pragma unroll
        for (int j = 0; j < 16; j++) {
            float s = colsum[j];
            s += __shfl_xor_sync(0xffffffffu, s, 4);
            s += __shfl_xor_sync(0xffffffffu, s, 8);
            s += __shfl_xor_sync(0xffffffffu, s, 16);
            if ((lane >> 2) == 0) {
                int e = wn * 64 + (j >> 1) * 8 + (lane & 3) * 2 + (j & 1);
                int hh = e >> 4, jj = e & 15;
                atomicAdd(&g_ksum[hh * DD + (rB << 4) + jj], s);
            }
        }
        return;
    }

    // ---- v path: +bias -> g_Vh fp16 ----
#pragma unroll
    for (int mi = 0; mi < 4; mi++) {
#pragma unroll
        for (int ni = 0; ni < 8; ni++) {
            int grow = m0 + wm * 64 + mi * 16 + (lane >> 2);
            int gcol = n0 + wn * 64 + ni * 8 + (lane & 3) * 2;
            int e = gcol & 127;
            int hh = e >> 4, jj = e & 15;
            float b0 = bias[gcol], b1 = bias[gcol + 1];
#pragma unroll
            for (int rr2 = 0; rr2 < 2; rr2++) {
                int rc = grow + rr2 * 8;
                int r = rc >> 11, c = rc & (CC - 1);
                float a0 = (rr2 ? acc[mi][ni][2] : acc[mi][ni][0]) + b0;
                float a1 = (rr2 ? acc[mi][ni][3] : acc[mi][ni][1]) + b1;
                *(__half2*)&g_Vh[((size_t)hh * CC + c) * DD + (r << 4) + jj] =
                    __floats2half2_rn(a0, a1);
            }
        }
    }
}

// ---------------------------------------------------------------------------
// MEGA kernel: blockIdx.x in [0, 3584):
//   [0,512):     ctx (TN)  — per head 8x8 blocks; signals g_ctx_done
//   [512,2560):  attn (NT) — per head 16x16 blocks
//   [2560,3584): out (NT)  — per head 16x8 blocks; waits for ctx
// ---------------------------------------------------------------------------
__global__ __launch_bounds__(NTHR, 2) void mega_kernel(float* __restrict__ attn_out,
                                                       float* __restrict__ out) {
    extern __shared__ __align__(16) hf smem[];
    const int tid = threadIdx.x, lane = tid & 31, warp = tid >> 5;
    const int wm = warp >> 1, wn = warp & 1;
    const int id = blockIdx.x;

    float acc[4][8][4];
#pragma unroll
    for (int i = 0; i < 4; i++)
#pragma unroll
        for (int j = 0; j < 8; j++)
#pragma unroll
            for (int q = 0; q < 4; q++) acc[i][j][q] = 0.f;

    if (id < 512) {
        // ---- ctx: z in [0,8), by in [0,8), bx in [0,8) ----
        int z = id >> 6, by = (id >> 3) & 7, bx = id & 7;
        int m0 = by * BM, n0 = bx * BN;
        gemm_tn(g_Vh + (size_t)z * CC * DD, g_Kh + (size_t)z * CC * DD,
                DD, DD, CC, m0, n0, smem, tid, lane, wm, wn, acc);
        hf* bh = g_CTh + (size_t)z * DD * DD;
#pragma unroll
        for (int mi = 0; mi < 4; mi++)
#pragma unroll
            for (int ni = 0; ni < 8; ni++) {
                int grow = m0 + wm * 64 + mi * 16 + (lane >> 2);
                int gcol = n0 + wn * 64 + ni * 8 + (lane & 3) * 2;
                *(__half2*)&bh[(size_t)grow * DD + gcol] =
                    __floats2half2_rn(acc[mi][ni][0], acc[mi][ni][1]);
                *(__half2*)&bh[(size_t)(grow + 8) * DD + gcol] =
                    __floats2half2_rn(acc[mi][ni][2], acc[mi][ni][3]);
            }
        __syncthreads();
        if (tid == 0) {
            __threadfence();
            atomicAdd(&g_ctx_done, 1);
        }
    } else if (id < 2560) {
        // ---- attn: z in [0,8), by in [0,16), bx in [0,16) ----
        int id2 = id - 512;
        int z = id2 >> 8, by = (id2 >> 4) & 15, bx = id2 & 15;
        int m0 = by * BM, n0 = bx * BN;
        gemm_nt(g_Qh + (size_t)z * CC * DD, g_Kh + (size_t)z * CC * DD,
                DD, DD, DD, m0, n0, smem, tid, lane, wm, wn, acc);
        float* base = attn_out + (size_t)z * CC * CC;
#pragma unroll
        for (int mi = 0; mi < 4; mi++)
#pragma unroll
            for (int ni = 0; ni < 8; ni++) {
                int grow = m0 + wm * 64 + mi * 16 + (lane >> 2);
                int gcol = n0 + wn * 64 + ni * 8 + (lane & 3) * 2;
                *(float2*)&base[(size_t)grow * CC + gcol] =
                    make_float2(acc[mi][ni][0], acc[mi][ni][1]);
                *(float2*)&base[(size_t)(grow + 8) * CC + gcol] =
                    make_float2(acc[mi][ni][2], acc[mi][ni][3]);
            }
    } else {
        // ---- out: z in [0,8), by in [0,16), bx in [0,8); waits for ctx ----
        if (tid == 0) {
            while (atomicAdd(&g_ctx_done, 0) < 512) { __nanosleep(128); }
        }
        __syncthreads();
        __threadfence();

        int id2 = id - 2560;                 // [0,1024)
        int z = id2 >> 7, by = (id2 >> 3) & 15, bx = id2 & 7;
        int m0 = by * BM, n0 = bx * BN;
        gemm_nt(g_Qh + (size_t)z * CC * DD, g_CTh + (size_t)z * DD * DD,
                DD, DD, DD, m0, n0, smem, tid, lane, wm, wn, acc);
#pragma unroll
        for (int mi = 0; mi < 4; mi++)
#pragma unroll
            for (int ni = 0; ni < 8; ni++) {
                int grow = m0 + wm * 64 + mi * 16 + (lane >> 2);
                int gcol = n0 + wn * 64 + ni * 8 + (lane & 3) * 2;
                int r = gcol >> 4, j = gcol & 15;
#pragma unroll
                for (int rr2 = 0; rr2 < 2; rr2++) {
                    int c = grow + rr2 * 8;
                    float a0 = rr2 ? acc[mi][ni][2] : acc[mi][ni][0];
                    float a1 = rr2 ? acc[mi][ni][3] : acc[mi][ni][1];
                    *(float2*)&out[(((size_t)r * CC + c) << 7) + z * HDIM + j] =
                        make_float2(a0, a1);
                }
            }
    }
}

// ---------------------------------------------------------------------------
// prep: x->fp16 (16384), W->fp16 (48), bias+flag (2), zero ksum (32)
// ---------------------------------------------------------------------------
__global__ __launch_bounds__(256) void prep_kernel(
    const float* __restrict__ x, const float* __restrict__ Wq,
    const float* __restrict__ Wk, const float* __restrict__ Wv,
    const float* __restrict__ bq, const float* __restrict__ bk,
    const float* __restrict__ bv) {
    int b = blockIdx.x, tid = threadIdx.x;
    if (b < 16384) {
        int i = b * 256 + tid;
        float4 v = *(const float4*)(x + (size_t)i * 4);
        *(__half2*)(g_xh + (size_t)i * 4) = __floats2half2_rn(v.x, v.y);
        *(__half2*)(g_xh + (size_t)i * 4 + 2) = __floats2half2_rn(v.z, v.w);
    } else if (b < 16432) {
        int q = (b - 16384) * 256 + tid;
        int w = q >> 12, j = q & 4095;
        const float* W = (w == 0) ? Wq : (w == 1) ? Wk : Wv;
        float4 v = *(const float4*)(W + j * 4);
        hf* dst = g_Wallh + w * EE * EE + j * 4;
        *(__half2*)dst = __floats2half2_rn(v.x, v.y);
        *(__half2*)(dst + 2) = __floats2half2_rn(v.z, v.w);
    } else if (b < 16434) {
        int i = (b - 16432) * 256 + tid;
        if (i < 384)
            g_ball[i] = (i < 128) ? bq[i] : (i < 256) ? bk[i - 128] : bv[i - 256];
        if (b == 16432 && tid == 0) g_ctx_done = 0;
    } else {
        g_ksum[(b - 16434) * 256 + tid] = 0.f;
    }
}

// ---------------------------------------------------------------------------
// ksoft: Kh = Kexp * (1 / ksum[d])  — pure scale pass, 8 halfs per thread
// ---------------------------------------------------------------------------
__global__ __launch_bounds__(256) void ksoft_kernel() {
    size_t i8 = (size_t)blockIdx.x * 256 + threadIdx.x;
    size_t base = i8 * 8;
    int h = (int)(base >> 21);
    int d = (int)(base & (DD - 1));
    float4 raw = *(const float4*)(g_Kexp + base);
    const __half2* h2 = (const __half2*)&raw;
    const float* sums = g_ksum + h * DD + d;
    float4 sv0 = *(const float4*)sums;
    float4 sv1 = *(const float4*)(sums + 4);
    float iv[8] = {__fdividef(1.f, sv0.x), __fdividef(1.f, sv0.y),
                   __fdividef(1.f, sv0.z), __fdividef(1.f, sv0.w),
                   __fdividef(1.f, sv1.x), __fdividef(1.f, sv1.y),
                   __fdividef(1.f, sv1.z), __fdividef(1.f, sv1.w)};
    __half2 outv[4];
#pragma unroll
    for (int j = 0; j < 4; j++) {
        float2 f = __half22float2(h2[j]);
        outv[j] = __floats2half2_rn(f.x * iv[2 * j], f.y * iv[2 * j + 1]);
    }
    *(float4*)(g_Kh + base) = *(float4*)outv;
}

// ---------------------------------------------------------------------------
// launch
// ---------------------------------------------------------------------------
extern "C" void kernel_launch(void* const* d_in, const int* in_sizes, int n_in,
                              void* d_out, int out_size) {
    const float* x  = (const float*)d_in[0];
    const float* Wq = (const float*)d_in[1];
    const float* bq = (const float*)d_in[2];
    const float* Wk = (const float*)d_in[3];
    const float* bk = (const float*)d_in[4];
    const float* Wv = (const float*)d_in[5];
    const float* bv = (const float*)d_in[6];
    float* out = (float*)d_out;

    cudaFuncSetAttribute(proj_kernel, cudaFuncAttributeMaxDynamicSharedMemorySize, SMEM_BYTES);
    cudaFuncSetAttribute(mega_kernel, cudaFuncAttributeMaxDynamicSharedMemorySize, SMEM_BYTES);

    dim3 t256(256);
    dim3 t128(NTHR);

    // 1) prep (x/W fp16, bias, zero ksum + ctx flag)
    prep_kernel<<<16466, t256>>>(x, Wq, Wk, Wv, bq, bk, bv);

    // 2) fused projection (q softmax on N-block 0; k exp + column sums on N-block 1)
    proj_kernel<<<dim3(3, (RR * CC) / BM, 1), t128, SMEM_BYTES>>>();

    // 3) k softmax apply (pure scale)
    ksoft_kernel<<<HH * CC * DD / 8 / 256, t256>>>();

    // 4) mega: ctx (512) + attn (2048) + out (1024, waits on ctx)
    mega_kernel<<<3584, t128, SMEM_BYTES>>>(out + (size_t)RR * CC * EE, out);
}